// round 2
// baseline (speedup 1.0000x reference)
#include <cuda_runtime.h>

#define D 128
#define N_NODES_MAX 50000
#define E_MAX 600000

// Scratch (device globals — no allocation allowed)
__device__ float g_h[N_NODES_MAX * D];      // h = x @ W^T
__device__ float g_ssrc[N_NODES_MAX];       // h @ a[:128]
__device__ float g_sdst[N_NODES_MAX];       // h @ a[128:]
__device__ int   g_cnt[N_NODES_MAX];        // in-degree histogram
__device__ int   g_off[N_NODES_MAX + 1];    // CSR offsets (by dst)
__device__ int   g_cursor[N_NODES_MAX];     // scatter cursors
__device__ int   g_bsum[64];                // per-block scan sums
__device__ int   g_boff[65];                // scanned block sums
__device__ int   g_srcs[E_MAX];             // src ids sorted by dst

// ---------------- packed f32x2 helpers (sm_103a FFMA2) ----------------
__device__ __forceinline__ unsigned long long dup2(float v) {
    unsigned long long r;
    asm("mov.b64 %0, {%1, %1};" : "=l"(r) : "f"(v));
    return r;
}
__device__ __forceinline__ void fma2(unsigned long long& d, unsigned long long a,
                                     unsigned long long b) {
    asm("fma.rn.f32x2 %0, %1, %2, %0;" : "+l"(d) : "l"(a), "l"(b));
}
__device__ __forceinline__ float2 unpk2(unsigned long long v) {
    float2 f;
    asm("mov.b64 {%0, %1}, %2;" : "=f"(f.x), "=f"(f.y) : "l"(v));
    return f;
}

// ---------------------------------------------------------------------------
// 1) Histogram of dst
// ---------------------------------------------------------------------------
__global__ void zero_cnt_kernel(int N) {
    int i = blockIdx.x * blockDim.x + threadIdx.x;
    if (i < N) g_cnt[i] = 0;
}
__global__ void hist_kernel(const int* __restrict__ ei, int E) {
    int e = blockIdx.x * blockDim.x + threadIdx.x;
    if (e < E) atomicAdd(&g_cnt[ei[E + e]], 1);
}

// ---------------------------------------------------------------------------
// 2) Two-level exclusive scan of g_cnt -> g_off, g_cursor
// ---------------------------------------------------------------------------
__global__ void scan_local_kernel(int N) {
    __shared__ int wsum[32];
    int tid = threadIdx.x;
    int i = blockIdx.x * 1024 + tid;
    int v = (i < N) ? g_cnt[i] : 0;
    int lane = tid & 31, wid = tid >> 5;
    int s = v;
    #pragma unroll
    for (int o = 1; o < 32; o <<= 1) {
        int t = __shfl_up_sync(0xffffffffu, s, o);
        if (lane >= o) s += t;
    }
    if (lane == 31) wsum[wid] = s;
    __syncthreads();
    if (wid == 0) {
        int ws = wsum[lane];
        #pragma unroll
        for (int o = 1; o < 32; o <<= 1) {
            int t = __shfl_up_sync(0xffffffffu, ws, o);
            if (lane >= o) ws += t;
        }
        wsum[lane] = ws;
    }
    __syncthreads();
    int excl = s - v + (wid ? wsum[wid - 1] : 0);
    if (i < N) g_off[i] = excl;
    if (tid == 1023) g_bsum[blockIdx.x] = excl + v;
}
__global__ void scan_bsum_kernel(int nb) {
    __shared__ int s[65];
    int tid = threadIdx.x;
    if (tid < nb) s[tid] = g_bsum[tid];
    __syncthreads();
    if (tid == 0) {
        int acc = 0;
        for (int b = 0; b < nb; b++) { int t = s[b]; s[b] = acc; acc += t; }
        s[nb] = acc;
    }
    __syncthreads();
    if (tid <= nb) g_boff[tid] = s[tid];
}
__global__ void scan_add_kernel(int N, int nb) {
    int i = blockIdx.x * blockDim.x + threadIdx.x;
    if (i < N) {
        int o = g_off[i] + g_boff[i >> 10];
        g_off[i] = o;
        g_cursor[i] = o;
    }
    if (i == 0) g_off[N] = g_boff[nb];
}

// ---------------------------------------------------------------------------
// 3) Scatter edges into dst-sorted order
// ---------------------------------------------------------------------------
__global__ void sort_kernel(const int* __restrict__ ei, int E) {
    int e = blockIdx.x * blockDim.x + threadIdx.x;
    if (e >= E) return;
    int dst = ei[E + e];
    int pos = atomicAdd(&g_cursor[dst], 1);
    g_srcs[pos] = ei[e];
}

// ---------------------------------------------------------------------------
// 4) GEMM h = x @ W^T + fused s_src/s_dst, packed f32x2 FFMA2 inner loop.
// Block: 64 rows x 128 cols, 256 threads. Thread (ty,tx): rows ty*8..+7 as
// 4 row-pairs (packed accumulators), cols tx*4..+3.
// Smem: XsT[128][64] (X transposed: row-pairs = one ld.shared.v2) +
//       Wt[128][132]  (W transposed, padded).
// ---------------------------------------------------------------------------
__global__ __launch_bounds__(256, 2) void gemm_s_kernel(
    const float* __restrict__ x, const float* __restrict__ W,
    const float* __restrict__ a, int N)
{
    extern __shared__ float sm[];
    float* XsT = sm;                  // 128 * 64   (XsT[k][r] = x[row0+r][k])
    float* Wt  = sm + 128 * 64;       // 128 * 132  (Wt[k][j]  = W[j][k])
    const int tid = threadIdx.x;
    const int tx = tid & 31;
    const int ty = tid >> 5;
    const int row0 = blockIdx.x * 64;

    // Stage W transposed
    const float4* W4 = (const float4*)W;
    for (int idx = tid; idx < D * (D / 4); idx += 256) {
        int j = idx >> 5;
        int k = (idx & 31) * 4;
        float4 w = W4[idx];
        Wt[(k + 0) * 132 + j] = w.x;
        Wt[(k + 1) * 132 + j] = w.y;
        Wt[(k + 2) * 132 + j] = w.z;
        Wt[(k + 3) * 132 + j] = w.w;
    }
    // Stage X transposed (zero-pad tail rows)
    const float4* x4 = (const float4*)x;
    for (int idx = tid; idx < 64 * (D / 4); idx += 256) {
        int r = idx >> 5;
        int k4 = idx & 31;
        float4 v = make_float4(0.f, 0.f, 0.f, 0.f);
        if (row0 + r < N) v = x4[(row0 + r) * (D / 4) + k4];
        XsT[(k4 * 4 + 0) * 64 + r] = v.x;
        XsT[(k4 * 4 + 1) * 64 + r] = v.y;
        XsT[(k4 * 4 + 2) * 64 + r] = v.z;
        XsT[(k4 * 4 + 3) * 64 + r] = v.w;
    }
    __syncthreads();

    unsigned long long acc2[4][4];   // [row-pair][col] packed {row2r2, row2r2+1}
    #pragma unroll
    for (int r2 = 0; r2 < 4; r2++)
        #pragma unroll
        for (int c = 0; c < 4; c++) acc2[r2][c] = dup2(0.f);

    #pragma unroll 4
    for (int k = 0; k < D; k++) {
        float4 wv = *(const float4*)&Wt[k * 132 + tx * 4];   // conflict-free
        unsigned long long w0 = dup2(wv.x), w1 = dup2(wv.y);
        unsigned long long w2 = dup2(wv.z), w3 = dup2(wv.w);
        const float* xb = &XsT[k * 64 + ty * 8];
        #pragma unroll
        for (int r2 = 0; r2 < 4; r2++) {
            unsigned long long xx = *(const unsigned long long*)&xb[r2 * 2]; // broadcast v2
            fma2(acc2[r2][0], xx, w0);
            fma2(acc2[r2][1], xx, w1);
            fma2(acc2[r2][2], xx, w2);
            fma2(acc2[r2][3], xx, w3);
        }
    }

    float4 asrc = *(const float4*)&a[tx * 4];
    float4 adst = *(const float4*)&a[D + tx * 4];

    #pragma unroll
    for (int r2 = 0; r2 < 4; r2++) {
        float2 c0 = unpk2(acc2[r2][0]);
        float2 c1 = unpk2(acc2[r2][1]);
        float2 c2 = unpk2(acc2[r2][2]);
        float2 c3 = unpk2(acc2[r2][3]);
        #pragma unroll
        for (int half = 0; half < 2; half++) {
            int row = row0 + ty * 8 + r2 * 2 + half;
            if (row < N) {
                float4 hv = half == 0 ? make_float4(c0.x, c1.x, c2.x, c3.x)
                                      : make_float4(c0.y, c1.y, c2.y, c3.y);
                *(float4*)&g_h[row * D + tx * 4] = hv;
                float ps = hv.x * asrc.x + hv.y * asrc.y + hv.z * asrc.z + hv.w * asrc.w;
                float pd = hv.x * adst.x + hv.y * adst.y + hv.z * adst.z + hv.w * adst.w;
                #pragma unroll
                for (int off = 16; off > 0; off >>= 1) {
                    ps += __shfl_xor_sync(0xffffffffu, ps, off);
                    pd += __shfl_xor_sync(0xffffffffu, pd, off);
                }
                if (tx == 0) { g_ssrc[row] = ps; g_sdst[row] = pd; }
            }
        }
    }
}

// ---------------------------------------------------------------------------
// 5) Fused aggregate + residual + LayerNorm. One warp per dst node:
//    agg = sum_e exp(leaky(ssrc[src]+sdst[dst])) * h[src]  /  sum_e exp(...)
// ---------------------------------------------------------------------------
__global__ __launch_bounds__(256) void agg_ln_kernel(
    const float* __restrict__ x, const float* __restrict__ gamma,
    const float* __restrict__ beta, float* __restrict__ out, int N)
{
    int gw = (blockIdx.x * blockDim.x + threadIdx.x) >> 5;
    int lane = threadIdx.x & 31;
    if (gw >= N) return;
    int start = g_off[gw];
    int end = g_off[gw + 1];
    float sdst = g_sdst[gw];

    float a0 = 0.f, a1 = 0.f, a2 = 0.f, a3 = 0.f, z = 0.f;
    int src = (start < end) ? g_srcs[start] : 0;   // prefetch
    for (int e = start; e < end; e++) {
        int cur = src;
        if (e + 1 < end) src = g_srcs[e + 1];
        float v = g_ssrc[cur] + sdst;
        v = v > 0.f ? v : 0.2f * v;
        float ex = __expf(v);
        float4 hv = *(const float4*)&g_h[cur * D + lane * 4];
        z += ex;
        a0 += ex * hv.x;
        a1 += ex * hv.y;
        a2 += ex * hv.z;
        a3 += ex * hv.w;
    }
    float invz = (end > start) ? 1.f / z : 0.f;

    float4 xv = *(const float4*)&x[gw * D + lane * 4];
    float y0 = a0 * invz + xv.x, y1 = a1 * invz + xv.y;
    float y2 = a2 * invz + xv.z, y3 = a3 * invz + xv.w;

    float s = y0 + y1 + y2 + y3;
    #pragma unroll
    for (int off = 16; off > 0; off >>= 1) s += __shfl_xor_sync(0xffffffffu, s, off);
    float mean = s * (1.f / 128.f);
    float d0 = y0 - mean, d1 = y1 - mean, d2 = y2 - mean, d3 = y3 - mean;
    float q = d0 * d0 + d1 * d1 + d2 * d2 + d3 * d3;
    #pragma unroll
    for (int off = 16; off > 0; off >>= 1) q += __shfl_xor_sync(0xffffffffu, q, off);
    float inv = rsqrtf(q * (1.f / 128.f) + 1e-5f);

    float4 gv = *(const float4*)&gamma[lane * 4];
    float4 bv = *(const float4*)&beta[lane * 4];
    float4 o;
    o.x = d0 * inv * gv.x + bv.x;
    o.y = d1 * inv * gv.y + bv.y;
    o.z = d2 * inv * gv.z + bv.z;
    o.w = d3 * inv * gv.w + bv.w;
    *(float4*)&out[gw * D + lane * 4] = o;
}

// ---------------------------------------------------------------------------
extern "C" void kernel_launch(void* const* d_in, const int* in_sizes, int n_in,
                              void* d_out, int out_size) {
    const float* x     = (const float*)d_in[0];
    const int*   ei    = (const int*)d_in[1];
    const float* W     = (const float*)d_in[2];
    const float* a     = (const float*)d_in[3];
    const float* gamma = (const float*)d_in[4];
    const float* beta  = (const float*)d_in[5];
    float* out = (float*)d_out;

    int N = in_sizes[0] / D;
    int E = in_sizes[1] / 2;
    int nb = (N + 1023) / 1024;

    int smem = (128 * 64 + 128 * 132) * (int)sizeof(float);  // ~98 KB
    cudaFuncSetAttribute(gemm_s_kernel, cudaFuncAttributeMaxDynamicSharedMemorySize, smem);

    zero_cnt_kernel<<<(N + 255) / 256, 256>>>(N);
    hist_kernel<<<(E + 255) / 256, 256>>>(ei, E);
    scan_local_kernel<<<nb, 1024>>>(N);
    scan_bsum_kernel<<<1, 64>>>(nb);
    scan_add_kernel<<<(N + 255) / 256, 256>>>(N, nb);
    sort_kernel<<<(E + 255) / 256, 256>>>(ei, E);
    gemm_s_kernel<<<(N + 63) / 64, 256, smem>>>(x, W, a, N);
    agg_ln_kernel<<<(N * 32 + 255) / 256, 256>>>(x, gamma, beta, out, N);
}

// round 3
// speedup vs baseline: 1.8311x; 1.8311x over previous
#include <cuda_runtime.h>

#define D 128
#define N_NODES_MAX 50000
#define E_MAX 600000

// Scratch (device globals — no allocation allowed)
__device__ float g_h[N_NODES_MAX * D];      // h = x @ W^T
__device__ float g_ssrc[N_NODES_MAX];       // h @ a[:128]
__device__ float g_sdst[N_NODES_MAX];       // h @ a[128:]
__device__ int   g_cnt[N_NODES_MAX];        // in-degree histogram (ZERO invariant: zeroed at
                                            // module load; re-zeroed by scan_add each call)
__device__ int   g_off[N_NODES_MAX + 1];    // CSR offsets (by dst)
__device__ int   g_cursor[N_NODES_MAX];     // scatter cursors
__device__ int   g_bsum[64];                // per-1024-chunk sums
__device__ int   g_srcs[E_MAX];             // src ids sorted by dst

// ---------------- packed f32x2 helpers (sm_103a FFMA2) ----------------
__device__ __forceinline__ unsigned long long dup2(float v) {
    unsigned long long r;
    asm("mov.b64 %0, {%1, %1};" : "=l"(r) : "f"(v));
    return r;
}
__device__ __forceinline__ void fma2(unsigned long long& d, unsigned long long a,
                                     unsigned long long b) {
    asm("fma.rn.f32x2 %0, %1, %2, %0;" : "+l"(d) : "l"(a), "l"(b));
}
__device__ __forceinline__ float2 unpk2(unsigned long long v) {
    float2 f;
    asm("mov.b64 {%0, %1}, %2;" : "=f"(f.x), "=f"(f.y) : "l"(v));
    return f;
}

// ---------------------------------------------------------------------------
// 1) Histogram of dst (g_cnt arrives zeroed: module-load zero on first call,
//    re-zeroed by scan_add_kernel on every call thereafter).
// ---------------------------------------------------------------------------
__global__ void hist_kernel(const int* __restrict__ ei, int E) {
    int e = blockIdx.x * blockDim.x + threadIdx.x;
    if (e < E) atomicAdd(&g_cnt[ei[E + e]], 1);
}

// ---------------------------------------------------------------------------
// 2a) Local exclusive scan per 1024-chunk -> g_off (local), g_bsum[chunk]
// ---------------------------------------------------------------------------
__global__ void scan_local_kernel(int N) {
    __shared__ int wsum[32];
    int tid = threadIdx.x;
    int i = blockIdx.x * 1024 + tid;
    int v = (i < N) ? g_cnt[i] : 0;
    int lane = tid & 31, wid = tid >> 5;
    int s = v;
    #pragma unroll
    for (int o = 1; o < 32; o <<= 1) {
        int t = __shfl_up_sync(0xffffffffu, s, o);
        if (lane >= o) s += t;
    }
    if (lane == 31) wsum[wid] = s;
    __syncthreads();
    if (wid == 0) {
        int ws = wsum[lane];
        #pragma unroll
        for (int o = 1; o < 32; o <<= 1) {
            int t = __shfl_up_sync(0xffffffffu, ws, o);
            if (lane >= o) ws += t;
        }
        wsum[lane] = ws;
    }
    __syncthreads();
    int excl = s - v + (wid ? wsum[wid - 1] : 0);
    if (i < N) g_off[i] = excl;
    if (tid == 1023) g_bsum[blockIdx.x] = excl + v;
}

// ---------------------------------------------------------------------------
// 2b) Add chunk prefix (tiny per-block serial scan over <=49 sums), init
//     cursors, write g_off[N], and re-zero g_cnt for the next replay.
//     Each 256-thread block lies fully inside one 1024-chunk.
// ---------------------------------------------------------------------------
__global__ void scan_add_kernel(int N, int nb) {
    __shared__ int pre;
    int i = blockIdx.x * 256 + threadIdx.x;
    if (threadIdx.x == 0) {
        int seg = (blockIdx.x * 256) >> 10;
        int acc = 0;
        for (int b = 0; b < seg; b++) acc += g_bsum[b];
        pre = acc;
    }
    __syncthreads();
    if (i < N) {
        int c = g_cnt[i];
        int o = g_off[i] + pre;
        g_off[i] = o;
        g_cursor[i] = o;
        g_cnt[i] = 0;                      // restore ZERO invariant
        if (i == N - 1) g_off[N] = o + c;  // total edge count
    }
}

// ---------------------------------------------------------------------------
// 3) Scatter src ids into dst-sorted order
// ---------------------------------------------------------------------------
__global__ void sort_kernel(const int* __restrict__ ei, int E) {
    int e = blockIdx.x * blockDim.x + threadIdx.x;
    if (e >= E) return;
    int dst = ei[E + e];
    int pos = atomicAdd(&g_cursor[dst], 1);
    g_srcs[pos] = ei[e];
}

// ---------------------------------------------------------------------------
// 4) GEMM h = x @ W^T + fused s_src/s_dst, packed f32x2 FFMA2 inner loop.
// Block: 64 rows x 128 cols, 256 threads. Thread (ty,tx): rows ty*8..+7 as
// 4 row-pairs (packed accumulators), cols tx*4..+3.
// Smem: XsT[128][64]  (X transposed; staged with r-fast mapping -> conflict-free STS)
//       Wt [128][132] (W transposed, padded).
// ---------------------------------------------------------------------------
__global__ __launch_bounds__(256, 2) void gemm_s_kernel(
    const float* __restrict__ x, const float* __restrict__ W,
    const float* __restrict__ a, int N)
{
    extern __shared__ float sm[];
    float* XsT = sm;                  // 128 * 64   (XsT[k][r] = x[row0+r][k])
    float* Wt  = sm + 128 * 64;       // 128 * 132  (Wt[k][j]  = W[j][k])
    const int tid = threadIdx.x;
    const int tx = tid & 31;
    const int ty = tid >> 5;
    const int row0 = blockIdx.x * 64;

    // Stage W transposed (coalesced reads; 4-way STS conflict, one-time)
    const float4* W4 = (const float4*)W;
    for (int idx = tid; idx < D * (D / 4); idx += 256) {
        int j = idx >> 5;
        int k = (idx & 31) * 4;
        float4 w = W4[idx];
        Wt[(k + 0) * 132 + j] = w.x;
        Wt[(k + 1) * 132 + j] = w.y;
        Wt[(k + 2) * 132 + j] = w.z;
        Wt[(k + 3) * 132 + j] = w.w;
    }
    // Stage X transposed. r fast-varying: STS conflict-free (lanes hit
    // consecutive banks); global read pays 50% sector efficiency (one-time).
    const float4* x4 = (const float4*)x;
    for (int idx = tid; idx < 64 * (D / 4); idx += 256) {
        int r = idx & 63;
        int k4 = idx >> 6;
        float4 v = make_float4(0.f, 0.f, 0.f, 0.f);
        if (row0 + r < N) v = x4[(row0 + r) * (D / 4) + k4];
        XsT[(k4 * 4 + 0) * 64 + r] = v.x;
        XsT[(k4 * 4 + 1) * 64 + r] = v.y;
        XsT[(k4 * 4 + 2) * 64 + r] = v.z;
        XsT[(k4 * 4 + 3) * 64 + r] = v.w;
    }
    __syncthreads();

    unsigned long long acc2[4][4];   // [row-pair][col] packed {row 2r2, row 2r2+1}
    #pragma unroll
    for (int r2 = 0; r2 < 4; r2++)
        #pragma unroll
        for (int c = 0; c < 4; c++) acc2[r2][c] = dup2(0.f);

    #pragma unroll 4
    for (int k = 0; k < D; k++) {
        float4 wv = *(const float4*)&Wt[k * 132 + tx * 4];   // conflict-free
        unsigned long long w0 = dup2(wv.x), w1 = dup2(wv.y);
        unsigned long long w2 = dup2(wv.z), w3 = dup2(wv.w);
        const float* xb = &XsT[k * 64 + ty * 8];
        #pragma unroll
        for (int r2 = 0; r2 < 4; r2++) {
            unsigned long long xx = *(const unsigned long long*)&xb[r2 * 2]; // v2 broadcast
            fma2(acc2[r2][0], xx, w0);
            fma2(acc2[r2][1], xx, w1);
            fma2(acc2[r2][2], xx, w2);
            fma2(acc2[r2][3], xx, w3);
        }
    }

    float4 asrc = *(const float4*)&a[tx * 4];
    float4 adst = *(const float4*)&a[D + tx * 4];

    #pragma unroll
    for (int r2 = 0; r2 < 4; r2++) {
        float2 c0 = unpk2(acc2[r2][0]);
        float2 c1 = unpk2(acc2[r2][1]);
        float2 c2 = unpk2(acc2[r2][2]);
        float2 c3 = unpk2(acc2[r2][3]);
        #pragma unroll
        for (int half = 0; half < 2; half++) {
            int row = row0 + ty * 8 + r2 * 2 + half;
            if (row < N) {
                float4 hv = half == 0 ? make_float4(c0.x, c1.x, c2.x, c3.x)
                                      : make_float4(c0.y, c1.y, c2.y, c3.y);
                *(float4*)&g_h[row * D + tx * 4] = hv;
                float ps = hv.x * asrc.x + hv.y * asrc.y + hv.z * asrc.z + hv.w * asrc.w;
                float pd = hv.x * adst.x + hv.y * adst.y + hv.z * adst.z + hv.w * adst.w;
                #pragma unroll
                for (int off = 16; off > 0; off >>= 1) {
                    ps += __shfl_xor_sync(0xffffffffu, ps, off);
                    pd += __shfl_xor_sync(0xffffffffu, pd, off);
                }
                if (tx == 0) { g_ssrc[row] = ps; g_sdst[row] = pd; }
            }
        }
    }
}

// ---------------------------------------------------------------------------
// 5) Fused aggregate + residual + LayerNorm. One warp per dst node, edge loop
//    unrolled x4 with 4 independent h-row gathers in flight (MLP=4).
//    agg = sum_e exp(leaky(ssrc[src]+sdst)) * h[src] / sum_e exp(...)
// ---------------------------------------------------------------------------
__global__ __launch_bounds__(256) void agg_ln_kernel(
    const float* __restrict__ x, const float* __restrict__ gamma,
    const float* __restrict__ beta, float* __restrict__ out, int N)
{
    int gw = (blockIdx.x * blockDim.x + threadIdx.x) >> 5;
    int lane = threadIdx.x & 31;
    if (gw >= N) return;
    int start = g_off[gw];
    int end = g_off[gw + 1];
    float sdst = g_sdst[gw];

    float a0 = 0.f, a1 = 0.f, a2 = 0.f, a3 = 0.f, z = 0.f;
    int e = start;
    for (; e + 4 <= end; e += 4) {
        int s0 = g_srcs[e + 0];
        int s1 = g_srcs[e + 1];
        int s2 = g_srcs[e + 2];
        int s3 = g_srcs[e + 3];
        float4 h0 = *(const float4*)&g_h[s0 * D + lane * 4];
        float4 h1 = *(const float4*)&g_h[s1 * D + lane * 4];
        float4 h2 = *(const float4*)&g_h[s2 * D + lane * 4];
        float4 h3 = *(const float4*)&g_h[s3 * D + lane * 4];
        float v0 = g_ssrc[s0] + sdst; v0 = v0 > 0.f ? v0 : 0.2f * v0;
        float v1 = g_ssrc[s1] + sdst; v1 = v1 > 0.f ? v1 : 0.2f * v1;
        float v2 = g_ssrc[s2] + sdst; v2 = v2 > 0.f ? v2 : 0.2f * v2;
        float v3 = g_ssrc[s3] + sdst; v3 = v3 > 0.f ? v3 : 0.2f * v3;
        float e0 = __expf(v0), e1 = __expf(v1), e2 = __expf(v2), e3 = __expf(v3);
        z += (e0 + e1) + (e2 + e3);
        a0 += e0 * h0.x + e1 * h1.x + e2 * h2.x + e3 * h3.x;
        a1 += e0 * h0.y + e1 * h1.y + e2 * h2.y + e3 * h3.y;
        a2 += e0 * h0.z + e1 * h1.z + e2 * h2.z + e3 * h3.z;
        a3 += e0 * h0.w + e1 * h1.w + e2 * h2.w + e3 * h3.w;
    }
    for (; e < end; e++) {
        int s0 = g_srcs[e];
        float4 h0 = *(const float4*)&g_h[s0 * D + lane * 4];
        float v0 = g_ssrc[s0] + sdst; v0 = v0 > 0.f ? v0 : 0.2f * v0;
        float e0 = __expf(v0);
        z += e0;
        a0 += e0 * h0.x; a1 += e0 * h0.y; a2 += e0 * h0.z; a3 += e0 * h0.w;
    }
    float invz = (end > start) ? 1.f / z : 0.f;

    float4 xv = *(const float4*)&x[gw * D + lane * 4];
    float y0 = a0 * invz + xv.x, y1 = a1 * invz + xv.y;
    float y2 = a2 * invz + xv.z, y3 = a3 * invz + xv.w;

    float s = y0 + y1 + y2 + y3;
    #pragma unroll
    for (int off = 16; off > 0; off >>= 1) s += __shfl_xor_sync(0xffffffffu, s, off);
    float mean = s * (1.f / 128.f);
    float d0 = y0 - mean, d1 = y1 - mean, d2 = y2 - mean, d3 = y3 - mean;
    float q = d0 * d0 + d1 * d1 + d2 * d2 + d3 * d3;
    #pragma unroll
    for (int off = 16; off > 0; off >>= 1) q += __shfl_xor_sync(0xffffffffu, q, off);
    float inv = rsqrtf(q * (1.f / 128.f) + 1e-5f);

    float4 gv = *(const float4*)&gamma[lane * 4];
    float4 bv = *(const float4*)&beta[lane * 4];
    float4 o;
    o.x = d0 * inv * gv.x + bv.x;
    o.y = d1 * inv * gv.y + bv.y;
    o.z = d2 * inv * gv.z + bv.z;
    o.w = d3 * inv * gv.w + bv.w;
    *(float4*)&out[gw * D + lane * 4] = o;
}

// ---------------------------------------------------------------------------
extern "C" void kernel_launch(void* const* d_in, const int* in_sizes, int n_in,
                              void* d_out, int out_size) {
    const float* x     = (const float*)d_in[0];
    const int*   ei    = (const int*)d_in[1];
    const float* W     = (const float*)d_in[2];
    const float* a     = (const float*)d_in[3];
    const float* gamma = (const float*)d_in[4];
    const float* beta  = (const float*)d_in[5];
    float* out = (float*)d_out;

    int N = in_sizes[0] / D;
    int E = in_sizes[1] / 2;
    int nb = (N + 1023) / 1024;

    int smem = (128 * 64 + 128 * 132) * (int)sizeof(float);  // ~98 KB
    cudaFuncSetAttribute(gemm_s_kernel, cudaFuncAttributeMaxDynamicSharedMemorySize, smem);

    hist_kernel<<<(E + 255) / 256, 256>>>(ei, E);
    scan_local_kernel<<<nb, 1024>>>(N);
    scan_add_kernel<<<(N + 255) / 256, 256>>>(N, nb);
    sort_kernel<<<(E + 255) / 256, 256>>>(ei, E);
    gemm_s_kernel<<<(N + 63) / 64, 256, smem>>>(x, W, a, N);
    agg_ln_kernel<<<(N * 32 + 255) / 256, 256>>>(x, gamma, beta, out, N);
}

// round 4
// speedup vs baseline: 2.0488x; 1.1189x over previous
#include <cuda_runtime.h>

#define D 128
#define N_NODES_MAX 50000
#define E_MAX 600000

// Scratch (device globals — no allocation allowed)
__device__ float g_h[N_NODES_MAX * D];      // h = x @ W^T
__device__ float g_ssrc[N_NODES_MAX];       // h @ a[:128]
__device__ float g_sdst[N_NODES_MAX];       // h @ a[128:]
__device__ int   g_cnt[N_NODES_MAX];        // in-degree histogram (ZERO invariant: zeroed at
                                            // module load; re-zeroed by scan_add each call)
__device__ int   g_off[N_NODES_MAX + 1];    // CSR offsets (by dst)
__device__ int   g_cursor[N_NODES_MAX];     // scatter cursors
__device__ int   g_bsum[64];                // per-1024-chunk sums
__device__ int   g_srcs[E_MAX];             // src ids sorted by dst

// ---------------- packed f32x2 helpers (sm_103a FFMA2) ----------------
__device__ __forceinline__ unsigned long long dup2(float v) {
    unsigned long long r;
    asm("mov.b64 %0, {%1, %1};" : "=l"(r) : "f"(v));
    return r;
}
__device__ __forceinline__ void fma2(unsigned long long& d, unsigned long long a,
                                     unsigned long long b) {
    asm("fma.rn.f32x2 %0, %1, %2, %0;" : "+l"(d) : "l"(a), "l"(b));
}
__device__ __forceinline__ float2 unpk2(unsigned long long v) {
    float2 f;
    asm("mov.b64 {%0, %1}, %2;" : "=f"(f.x), "=f"(f.y) : "l"(v));
    return f;
}

// ---------------------------------------------------------------------------
// 1) Histogram of dst — 4 edges/thread (int4 load, 4 independent atomics)
// ---------------------------------------------------------------------------
__global__ void hist_kernel(const int* __restrict__ ei, int E) {
    int t = blockIdx.x * blockDim.x + threadIdx.x;
    int e = t * 4;
    if (e + 4 <= E) {
        int4 d = *(const int4*)&ei[E + e];
        atomicAdd(&g_cnt[d.x], 1);
        atomicAdd(&g_cnt[d.y], 1);
        atomicAdd(&g_cnt[d.z], 1);
        atomicAdd(&g_cnt[d.w], 1);
    } else {
        for (int k = e; k < E; k++) atomicAdd(&g_cnt[ei[E + k]], 1);
    }
}

// ---------------------------------------------------------------------------
// 2a) Local exclusive scan per 1024-chunk -> g_off (local), g_bsum[chunk]
// ---------------------------------------------------------------------------
__global__ void scan_local_kernel(int N) {
    __shared__ int wsum[32];
    int tid = threadIdx.x;
    int i = blockIdx.x * 1024 + tid;
    int v = (i < N) ? g_cnt[i] : 0;
    int lane = tid & 31, wid = tid >> 5;
    int s = v;
    #pragma unroll
    for (int o = 1; o < 32; o <<= 1) {
        int t = __shfl_up_sync(0xffffffffu, s, o);
        if (lane >= o) s += t;
    }
    if (lane == 31) wsum[wid] = s;
    __syncthreads();
    if (wid == 0) {
        int ws = wsum[lane];
        #pragma unroll
        for (int o = 1; o < 32; o <<= 1) {
            int t = __shfl_up_sync(0xffffffffu, ws, o);
            if (lane >= o) ws += t;
        }
        wsum[lane] = ws;
    }
    __syncthreads();
    int excl = s - v + (wid ? wsum[wid - 1] : 0);
    if (i < N) g_off[i] = excl;
    if (tid == 1023) g_bsum[blockIdx.x] = excl + v;
}

// ---------------------------------------------------------------------------
// 2b) Add chunk prefix (serial scan over <=49 sums per block), init cursors,
//     write g_off[N], re-zero g_cnt. Block (256) fully inside one 1024-chunk.
// ---------------------------------------------------------------------------
__global__ void scan_add_kernel(int N, int nb) {
    __shared__ int pre;
    int i = blockIdx.x * 256 + threadIdx.x;
    if (threadIdx.x == 0) {
        int seg = (blockIdx.x * 256) >> 10;
        int acc = 0;
        for (int b = 0; b < seg; b++) acc += g_bsum[b];
        pre = acc;
    }
    __syncthreads();
    if (i < N) {
        int c = g_cnt[i];
        int o = g_off[i] + pre;
        g_off[i] = o;
        g_cursor[i] = o;
        g_cnt[i] = 0;                      // restore ZERO invariant
        if (i == N - 1) g_off[N] = o + c;  // total edge count
    }
}

// ---------------------------------------------------------------------------
// 3) Scatter src ids into dst-sorted order — 4 edges/thread (MLP=4)
// ---------------------------------------------------------------------------
__global__ void sort_kernel(const int* __restrict__ ei, int E) {
    int t = blockIdx.x * blockDim.x + threadIdx.x;
    int e = t * 4;
    if (e + 4 <= E) {
        int4 s = *(const int4*)&ei[e];
        int4 d = *(const int4*)&ei[E + e];
        int p0 = atomicAdd(&g_cursor[d.x], 1);
        int p1 = atomicAdd(&g_cursor[d.y], 1);
        int p2 = atomicAdd(&g_cursor[d.z], 1);
        int p3 = atomicAdd(&g_cursor[d.w], 1);
        g_srcs[p0] = s.x;
        g_srcs[p1] = s.y;
        g_srcs[p2] = s.z;
        g_srcs[p3] = s.w;
    } else {
        for (int k = e; k < E; k++) {
            int pos = atomicAdd(&g_cursor[ei[E + k]], 1);
            g_srcs[pos] = ei[k];
        }
    }
}

// ---------------------------------------------------------------------------
// 4) GEMM h = x @ W^T + fused s_src/s_dst, packed f32x2 FFMA2 inner loop.
// ---------------------------------------------------------------------------
__global__ __launch_bounds__(256, 2) void gemm_s_kernel(
    const float* __restrict__ x, const float* __restrict__ W,
    const float* __restrict__ a, int N)
{
    extern __shared__ float sm[];
    float* XsT = sm;                  // 128 * 64   (XsT[k][r] = x[row0+r][k])
    float* Wt  = sm + 128 * 64;       // 128 * 132  (Wt[k][j]  = W[j][k])
    const int tid = threadIdx.x;
    const int tx = tid & 31;
    const int ty = tid >> 5;
    const int row0 = blockIdx.x * 64;

    const float4* W4 = (const float4*)W;
    for (int idx = tid; idx < D * (D / 4); idx += 256) {
        int j = idx >> 5;
        int k = (idx & 31) * 4;
        float4 w = W4[idx];
        Wt[(k + 0) * 132 + j] = w.x;
        Wt[(k + 1) * 132 + j] = w.y;
        Wt[(k + 2) * 132 + j] = w.z;
        Wt[(k + 3) * 132 + j] = w.w;
    }
    const float4* x4 = (const float4*)x;
    for (int idx = tid; idx < 64 * (D / 4); idx += 256) {
        int r = idx & 63;
        int k4 = idx >> 6;
        float4 v = make_float4(0.f, 0.f, 0.f, 0.f);
        if (row0 + r < N) v = x4[(row0 + r) * (D / 4) + k4];
        XsT[(k4 * 4 + 0) * 64 + r] = v.x;
        XsT[(k4 * 4 + 1) * 64 + r] = v.y;
        XsT[(k4 * 4 + 2) * 64 + r] = v.z;
        XsT[(k4 * 4 + 3) * 64 + r] = v.w;
    }
    __syncthreads();

    unsigned long long acc2[4][4];
    #pragma unroll
    for (int r2 = 0; r2 < 4; r2++)
        #pragma unroll
        for (int c = 0; c < 4; c++) acc2[r2][c] = dup2(0.f);

    #pragma unroll 4
    for (int k = 0; k < D; k++) {
        float4 wv = *(const float4*)&Wt[k * 132 + tx * 4];
        unsigned long long w0 = dup2(wv.x), w1 = dup2(wv.y);
        unsigned long long w2 = dup2(wv.z), w3 = dup2(wv.w);
        const float* xb = &XsT[k * 64 + ty * 8];
        #pragma unroll
        for (int r2 = 0; r2 < 4; r2++) {
            unsigned long long xx = *(const unsigned long long*)&xb[r2 * 2];
            fma2(acc2[r2][0], xx, w0);
            fma2(acc2[r2][1], xx, w1);
            fma2(acc2[r2][2], xx, w2);
            fma2(acc2[r2][3], xx, w3);
        }
    }

    float4 asrc = *(const float4*)&a[tx * 4];
    float4 adst = *(const float4*)&a[D + tx * 4];

    #pragma unroll
    for (int r2 = 0; r2 < 4; r2++) {
        float2 c0 = unpk2(acc2[r2][0]);
        float2 c1 = unpk2(acc2[r2][1]);
        float2 c2 = unpk2(acc2[r2][2]);
        float2 c3 = unpk2(acc2[r2][3]);
        #pragma unroll
        for (int half = 0; half < 2; half++) {
            int row = row0 + ty * 8 + r2 * 2 + half;
            if (row < N) {
                float4 hv = half == 0 ? make_float4(c0.x, c1.x, c2.x, c3.x)
                                      : make_float4(c0.y, c1.y, c2.y, c3.y);
                *(float4*)&g_h[row * D + tx * 4] = hv;
                float ps = hv.x * asrc.x + hv.y * asrc.y + hv.z * asrc.z + hv.w * asrc.w;
                float pd = hv.x * adst.x + hv.y * adst.y + hv.z * adst.z + hv.w * adst.w;
                #pragma unroll
                for (int off = 16; off > 0; off >>= 1) {
                    ps += __shfl_xor_sync(0xffffffffu, ps, off);
                    pd += __shfl_xor_sync(0xffffffffu, pd, off);
                }
                if (tx == 0) { g_ssrc[row] = ps; g_sdst[row] = pd; }
            }
        }
    }
}

// ---------------------------------------------------------------------------
// 5) Fused aggregate + residual + LayerNorm. One warp per dst node, MLP=4.
// ---------------------------------------------------------------------------
__global__ __launch_bounds__(256) void agg_ln_kernel(
    const float* __restrict__ x, const float* __restrict__ gamma,
    const float* __restrict__ beta, float* __restrict__ out, int N)
{
    int gw = (blockIdx.x * blockDim.x + threadIdx.x) >> 5;
    int lane = threadIdx.x & 31;
    if (gw >= N) return;
    int start = g_off[gw];
    int end = g_off[gw + 1];
    float sdst = g_sdst[gw];

    float a0 = 0.f, a1 = 0.f, a2 = 0.f, a3 = 0.f, z = 0.f;
    int e = start;
    for (; e + 4 <= end; e += 4) {
        int s0 = g_srcs[e + 0];
        int s1 = g_srcs[e + 1];
        int s2 = g_srcs[e + 2];
        int s3 = g_srcs[e + 3];
        float4 h0 = *(const float4*)&g_h[s0 * D + lane * 4];
        float4 h1 = *(const float4*)&g_h[s1 * D + lane * 4];
        float4 h2 = *(const float4*)&g_h[s2 * D + lane * 4];
        float4 h3 = *(const float4*)&g_h[s3 * D + lane * 4];
        float v0 = g_ssrc[s0] + sdst; v0 = v0 > 0.f ? v0 : 0.2f * v0;
        float v1 = g_ssrc[s1] + sdst; v1 = v1 > 0.f ? v1 : 0.2f * v1;
        float v2 = g_ssrc[s2] + sdst; v2 = v2 > 0.f ? v2 : 0.2f * v2;
        float v3 = g_ssrc[s3] + sdst; v3 = v3 > 0.f ? v3 : 0.2f * v3;
        float e0 = __expf(v0), e1 = __expf(v1), e2 = __expf(v2), e3 = __expf(v3);
        z += (e0 + e1) + (e2 + e3);
        a0 += e0 * h0.x + e1 * h1.x + e2 * h2.x + e3 * h3.x;
        a1 += e0 * h0.y + e1 * h1.y + e2 * h2.y + e3 * h3.y;
        a2 += e0 * h0.z + e1 * h1.z + e2 * h2.z + e3 * h3.z;
        a3 += e0 * h0.w + e1 * h1.w + e2 * h2.w + e3 * h3.w;
    }
    for (; e < end; e++) {
        int s0 = g_srcs[e];
        float4 h0 = *(const float4*)&g_h[s0 * D + lane * 4];
        float v0 = g_ssrc[s0] + sdst; v0 = v0 > 0.f ? v0 : 0.2f * v0;
        float e0 = __expf(v0);
        z += e0;
        a0 += e0 * h0.x; a1 += e0 * h0.y; a2 += e0 * h0.z; a3 += e0 * h0.w;
    }
    float invz = (end > start) ? 1.f / z : 0.f;

    float4 xv = *(const float4*)&x[gw * D + lane * 4];
    float y0 = a0 * invz + xv.x, y1 = a1 * invz + xv.y;
    float y2 = a2 * invz + xv.z, y3 = a3 * invz + xv.w;

    float s = y0 + y1 + y2 + y3;
    #pragma unroll
    for (int off = 16; off > 0; off >>= 1) s += __shfl_xor_sync(0xffffffffu, s, off);
    float mean = s * (1.f / 128.f);
    float d0 = y0 - mean, d1 = y1 - mean, d2 = y2 - mean, d3 = y3 - mean;
    float q = d0 * d0 + d1 * d1 + d2 * d2 + d3 * d3;
    #pragma unroll
    for (int off = 16; off > 0; off >>= 1) q += __shfl_xor_sync(0xffffffffu, q, off);
    float inv = rsqrtf(q * (1.f / 128.f) + 1e-5f);

    float4 gv = *(const float4*)&gamma[lane * 4];
    float4 bv = *(const float4*)&beta[lane * 4];
    float4 o;
    o.x = d0 * inv * gv.x + bv.x;
    o.y = d1 * inv * gv.y + bv.y;
    o.z = d2 * inv * gv.z + bv.z;
    o.w = d3 * inv * gv.w + bv.w;
    *(float4*)&out[gw * D + lane * 4] = o;
}

// ---------------------------------------------------------------------------
// Launch: fork a side stream so the edge pipeline (hist/scan/sort, depends
// only on edge_index) runs concurrently with the GEMM (depends only on x/W/a).
// Event fork/join is graph-capture legal and builds a parallel-branch graph.
// ---------------------------------------------------------------------------
extern "C" void kernel_launch(void* const* d_in, const int* in_sizes, int n_in,
                              void* d_out, int out_size) {
    const float* x     = (const float*)d_in[0];
    const int*   ei    = (const int*)d_in[1];
    const float* W     = (const float*)d_in[2];
    const float* a     = (const float*)d_in[3];
    const float* gamma = (const float*)d_in[4];
    const float* beta  = (const float*)d_in[5];
    float* out = (float*)d_out;

    int N = in_sizes[0] / D;
    int E = in_sizes[1] / 2;
    int nb = (N + 1023) / 1024;
    int e4blocks = ((E + 3) / 4 + 255) / 256;

    static cudaStream_t s_side = nullptr;
    static cudaEvent_t ev_fork = nullptr, ev_join = nullptr;
    if (!s_side) {
        cudaStreamCreateWithFlags(&s_side, cudaStreamNonBlocking);
        cudaEventCreateWithFlags(&ev_fork, cudaEventDisableTiming);
        cudaEventCreateWithFlags(&ev_join, cudaEventDisableTiming);
    }

    int smem = (128 * 64 + 128 * 132) * (int)sizeof(float);  // ~98 KB
    cudaFuncSetAttribute(gemm_s_kernel, cudaFuncAttributeMaxDynamicSharedMemorySize, smem);

    // Fork: side stream runs the edge pipeline
    cudaEventRecord(ev_fork, 0);
    cudaStreamWaitEvent(s_side, ev_fork, 0);
    hist_kernel<<<e4blocks, 256, 0, s_side>>>(ei, E);
    scan_local_kernel<<<nb, 1024, 0, s_side>>>(N);
    scan_add_kernel<<<(N + 255) / 256, 256, 0, s_side>>>(N, nb);
    sort_kernel<<<e4blocks, 256, 0, s_side>>>(ei, E);
    cudaEventRecord(ev_join, s_side);

    // Main stream: GEMM concurrently
    gemm_s_kernel<<<(N + 63) / 64, 256, smem>>>(x, W, a, N);

    // Join, then fused aggregate+LN
    cudaStreamWaitEvent(0, ev_join, 0);
    agg_ln_kernel<<<(N * 32 + 255) / 256, 256>>>(x, gamma, beta, out, N);
}